// round 16
// baseline (speedup 1.0000x reference)
#include <cuda_runtime.h>

#define B_N   1024
#define C_N   128
#define I_N   16
#define E_N   10
#define NT3   816           // cubic monomials i0<=i1<=i2
#define NT2   136           // quadratic monomials
#define NT    968           // slab entries per (species, comp-half)
#define QOFF  NT3
#define LOFF  (NT3 + NT2)
#define NCOMP 4

// ---------------- device scratch (static globals; no allocation) ----------------
// task = {itemX, itemY, slabP_offset, slabQ_offset}; exactly B_N tasks
__device__ int4  g_task[B_N];
__device__ __align__(32) float g_U3S[NCOMP][NT3][8];
__device__ __align__(16) float g_U2S[NCOMP][NT2][4];
__device__ float g_U1S[NCOMP][I_N];

// ---------------- kernel A: task build (block 0) + U sym (blocks 1..32) ---------
__global__ void prep_kernel(const float* __restrict__ node_attrs,
                            const float* __restrict__ U3_l0,
                            const float* __restrict__ U3_l1,
                            const float* __restrict__ U2_l0,
                            const float* __restrict__ U2_l1,
                            const float* __restrict__ U1_l0,
                            const float* __restrict__ U1_l1) {
    int tid = threadIdx.x;   // 1024
    if (blockIdx.x == 0) {
        __shared__ int s_hist[E_N], s_off[E_N], s_start[E_N], s_end[E_N];
        __shared__ int s_evenbase[E_N], s_leftbase[E_N];
        __shared__ int s_npe;
        __shared__ int s_perm[B_N];
        if (tid < E_N) s_hist[tid] = 0;
        __syncthreads();
        const float* na = node_attrs + tid * E_N;
        int e = 0;
#pragma unroll
        for (int j = 0; j < E_N; j++) if (na[j] > 0.5f) e = j;
        atomicAdd(&s_hist[e], 1);
        __syncthreads();
        if (tid == 0) {
            int acc = 0, pe = 0, nl = 0;
            for (int j = 0; j < E_N; j++) {
                s_start[j] = acc; s_off[j] = acc;
                s_evenbase[j] = pe; s_leftbase[j] = nl;
                pe += s_hist[j] >> 1;
                nl += s_hist[j] & 1;
                acc += s_hist[j];
                s_end[j] = acc;
            }
            s_npe = pe;   // 2*pe + nl == B_N always
        }
        __syncthreads();
        int pos = atomicAdd(&s_off[e], 1);
        s_perm[pos] = tid;
        __syncthreads();
        int off = pos - s_start[e];
        int n_e = s_end[e] - s_start[e];
        if ((off & 1) == 0 && pos + 1 < s_end[e]) {
            // full same-species pair: two tasks (comp-half 0 and 1)
            int p = s_evenbase[e] + (off >> 1);
            int A = tid, B = s_perm[pos + 1];
            g_task[p]           = make_int4(A, B, e * NT,           e * NT);
            g_task[s_npe + p]   = make_int4(A, B, (E_N + e) * NT,   (E_N + e) * NT);
        } else if (off == n_e - 1 && (n_e & 1)) {
            // odd leftover: one task, all 4 comps (P = comps01 slab, Q = comps23)
            int l = s_leftbase[e];
            g_task[2 * s_npe + l] = make_int4(tid, tid, e * NT, (E_N + e) * NT);
        }
        return;
    }

    int gtid = (blockIdx.x - 1) * blockDim.x + tid;   // 0..32767

    if (gtid < NCOMP * NT3 * 8) {
        int k    = gtid & 7;
        int t    = (gtid >> 3) % NT3;
        int comp = gtid / (NT3 * 8);
        int rem = t, a = 0;
        for (int ap = 0; ap < I_N; ap++) {
            int sz = (I_N - ap) * (I_N - ap + 1) / 2;
            if (rem < sz) { a = ap; break; }
            rem -= sz;
        }
        int b = a;
        for (int bp = a; bp < I_N; bp++) {
            int sz = I_N - bp;
            if (rem < sz) { b = bp; break; }
            rem -= sz;
        }
        int c = b + rem;
        float inv = (a == c) ? (1.f / 6.f) : ((a == b || b == c) ? 0.5f : 1.f);
        int kN; const float* U;
        if (comp == 0) { kN = 5; U = U3_l0; }
        else           { kN = 7; U = U3_l1 + (comp - 1) * (I_N * I_N * I_N * 7); }
        float s = 0.f;
        if (k < kN) {
            auto at = [&](int i0, int i1, int i2) {
                return U[((i0 * I_N + i1) * I_N + i2) * kN + k];
            };
            s = at(a,b,c) + at(a,c,b) + at(b,a,c) + at(b,c,a) + at(c,a,b) + at(c,b,a);
            s *= inv;
        }
        g_U3S[comp][t][k] = s;
    }
    if (gtid < NCOMP * NT2 * 4) {
        int k    = gtid & 3;
        int t    = (gtid >> 2) % NT2;
        int comp = gtid / (NT2 * 4);
        int rem = t, a = 0;
        for (int ap = 0; ap < I_N; ap++) {
            int sz = I_N - ap;
            if (rem < sz) { a = ap; break; }
            rem -= sz;
        }
        int b = a + rem;
        int kN; const float* U;
        if (comp == 0) { kN = 2; U = U2_l0; }
        else           { kN = 3; U = U2_l1 + (comp - 1) * (I_N * I_N * 3); }
        float s = 0.f;
        if (k < kN) {
            s = U[(a * I_N + b) * kN + k];
            if (a != b) s += U[(b * I_N + a) * kN + k];
        }
        g_U2S[comp][t][k] = s;
    }
    if (gtid < NCOMP * I_N) {
        int comp = gtid / I_N, i = gtid % I_N;
        g_U1S[comp][i] = (comp == 0) ? U1_l0[i] : U1_l1[(comp - 1) * I_N + i];
    }
}

// ---------------- kernel B: fused fold + evaluation, block = channel ------------
// 1024 threads, EXACTLY one task per thread (no loop, no warp-0 tail).
// Generalized task: comps of slabP for itemX, comps of slabQ for itemY.
// Pair tasks: P==Q (same species+half); leftover tasks: X==Y, P=comps01, Q=comps23.
__global__ void __launch_bounds__(1024, 1) main_kernel(const float* __restrict__ a_i,
                                                       const float* __restrict__ W3_l0,
                                                       const float* __restrict__ W2_l0,
                                                       const float* __restrict__ W1_l0,
                                                       const float* __restrict__ W3_l1,
                                                       const float* __restrict__ W2_l1,
                                                       const float* __restrict__ W1_l1,
                                                       float* __restrict__ out) {
    extern __shared__ __align__(16) float2 s_raw[];   // [2 * E_N * NT] = 154.9 KB
    float2* s01 = s_raw;
    float2* s23 = s_raw + E_N * NT;
    __shared__ float sw30[E_N][5], sw31[E_N][7];
    __shared__ float sw20[E_N][2], sw21[E_N][3];
    __shared__ float sw10[E_N], sw11[E_N];
    int c   = blockIdx.x;
    int tid = threadIdx.x;

    // ---- stage per-channel species weights ----------------------------------
    if (tid < E_N * 5) sw30[tid / 5][tid % 5] = W3_l0[tid * C_N + c];
    if (tid < E_N * 7) sw31[tid / 7][tid % 7] = W3_l1[tid * C_N + c];
    if (tid < E_N * 2) sw20[tid / 2][tid % 2] = W2_l0[tid * C_N + c];
    if (tid < E_N * 3) sw21[tid / 3][tid % 3] = W2_l1[tid * C_N + c];
    if (tid < E_N) { sw10[tid] = W1_l0[tid * C_N + c]; sw11[tid] = W1_l1[tid * C_N + c]; }
    __syncthreads();

    // ---- fold: coefficients for all species, straight into SMEM -------------
    for (int t = tid; t < NT3; t += 1024) {
        float4 A0 = reinterpret_cast<const float4*>(&g_U3S[0][t][0])[0];
        float4 A1 = reinterpret_cast<const float4*>(&g_U3S[0][t][0])[1];
        float4 B0 = reinterpret_cast<const float4*>(&g_U3S[1][t][0])[0];
        float4 B1 = reinterpret_cast<const float4*>(&g_U3S[1][t][0])[1];
        float4 C0 = reinterpret_cast<const float4*>(&g_U3S[2][t][0])[0];
        float4 C1 = reinterpret_cast<const float4*>(&g_U3S[2][t][0])[1];
        float4 D0 = reinterpret_cast<const float4*>(&g_U3S[3][t][0])[0];
        float4 D1 = reinterpret_cast<const float4*>(&g_U3S[3][t][0])[1];
#pragma unroll
        for (int e = 0; e < E_N; e++) {
            float c0 = A0.x*sw30[e][0] + A0.y*sw30[e][1] + A0.z*sw30[e][2]
                     + A0.w*sw30[e][3] + A1.x*sw30[e][4];
            float c1 = B0.x*sw31[e][0] + B0.y*sw31[e][1] + B0.z*sw31[e][2]
                     + B0.w*sw31[e][3] + B1.x*sw31[e][4] + B1.y*sw31[e][5] + B1.z*sw31[e][6];
            float c2 = C0.x*sw31[e][0] + C0.y*sw31[e][1] + C0.z*sw31[e][2]
                     + C0.w*sw31[e][3] + C1.x*sw31[e][4] + C1.y*sw31[e][5] + C1.z*sw31[e][6];
            float c3 = D0.x*sw31[e][0] + D0.y*sw31[e][1] + D0.z*sw31[e][2]
                     + D0.w*sw31[e][3] + D1.x*sw31[e][4] + D1.y*sw31[e][5] + D1.z*sw31[e][6];
            s01[e * NT + t] = make_float2(c0, c1);
            s23[e * NT + t] = make_float2(c2, c3);
        }
    }
    for (int t = tid; t < NT2; t += 1024) {
        float4 Q0 = reinterpret_cast<const float4*>(&g_U2S[0][t][0])[0];
        float4 Q1 = reinterpret_cast<const float4*>(&g_U2S[1][t][0])[0];
        float4 Q2 = reinterpret_cast<const float4*>(&g_U2S[2][t][0])[0];
        float4 Q3 = reinterpret_cast<const float4*>(&g_U2S[3][t][0])[0];
#pragma unroll
        for (int e = 0; e < E_N; e++) {
            float c0 = Q0.x*sw20[e][0] + Q0.y*sw20[e][1];
            float c1 = Q1.x*sw21[e][0] + Q1.y*sw21[e][1] + Q1.z*sw21[e][2];
            float c2 = Q2.x*sw21[e][0] + Q2.y*sw21[e][1] + Q2.z*sw21[e][2];
            float c3 = Q3.x*sw21[e][0] + Q3.y*sw21[e][1] + Q3.z*sw21[e][2];
            s01[e * NT + QOFF + t] = make_float2(c0, c1);
            s23[e * NT + QOFF + t] = make_float2(c2, c3);
        }
    }
    if (tid < I_N) {
        int i = tid;
#pragma unroll
        for (int e = 0; e < E_N; e++) {
            s01[e * NT + LOFF + i] =
                make_float2(g_U1S[0][i] * sw10[e], g_U1S[1][i] * sw11[e]);
            s23[e * NT + LOFF + i] =
                make_float2(g_U1S[2][i] * sw11[e], g_U1S[3][i] * sw11[e]);
        }
    }
    __syncthreads();

    // ---- eval: one generalized task per thread -------------------------------
    int4 tk = g_task[tid];
    const float2* baseP = s_raw + tk.z;
    const float2* baseQ = s_raw + tk.w;

    float x0[16], x1[16];
    {
        const float4* xp = reinterpret_cast<const float4*>(a_i + (tk.x * C_N + c) * I_N);
        float4 v0 = xp[0], v1 = xp[1], v2 = xp[2], v3 = xp[3];
        x0[0]=v0.x;  x0[1]=v0.y;  x0[2]=v0.z;  x0[3]=v0.w;
        x0[4]=v1.x;  x0[5]=v1.y;  x0[6]=v1.z;  x0[7]=v1.w;
        x0[8]=v2.x;  x0[9]=v2.y;  x0[10]=v2.z; x0[11]=v2.w;
        x0[12]=v3.x; x0[13]=v3.y; x0[14]=v3.z; x0[15]=v3.w;
    }
    {
        const float4* xp = reinterpret_cast<const float4*>(a_i + (tk.y * C_N + c) * I_N);
        float4 v0 = xp[0], v1 = xp[1], v2 = xp[2], v3 = xp[3];
        x1[0]=v0.x;  x1[1]=v0.y;  x1[2]=v0.z;  x1[3]=v0.w;
        x1[4]=v1.x;  x1[5]=v1.y;  x1[6]=v1.z;  x1[7]=v1.w;
        x1[8]=v2.x;  x1[9]=v2.y;  x1[10]=v2.z; x1[11]=v2.w;
        x1[12]=v3.x; x1[13]=v3.y; x1[14]=v3.z; x1[15]=v3.w;
    }

    // comps u/v of slabP for item X; comps u/v of slabQ for item Y
    float ouX = 0.f, ovX = 0.f, ouY = 0.f, ovY = 0.f;
    int t = 0, tp = 0;
#pragma unroll
    for (int a = 0; a < I_N; a++) {
        float t2uX, t2vX, t2uY, t2vY;
        float2 clP = baseP[LOFF + a];
        float2 clQ = baseQ[LOFF + a];
#pragma unroll
        for (int b2 = a; b2 < I_N; b2++) {
            float2 cqP = baseP[QOFF + tp];
            float2 cqQ = baseQ[QOFF + tp];
            tp++;
            float t3uX, t3vX, t3uY, t3vY;
            {
                float2 cfP = baseP[t];
                float2 cfQ = baseQ[t];
                t++;
                t3uX = fmaf(cfP.x, x0[b2], cqP.x);  t3uY = fmaf(cfQ.x, x1[b2], cqQ.x);
                t3vX = fmaf(cfP.y, x0[b2], cqP.y);  t3vY = fmaf(cfQ.y, x1[b2], cqQ.y);
            }
#pragma unroll
            for (int c3 = b2 + 1; c3 < I_N; c3++) {
                float2 cfP = baseP[t];
                float2 cfQ = baseQ[t];
                t++;
                t3uX = fmaf(cfP.x, x0[c3], t3uX);  t3uY = fmaf(cfQ.x, x1[c3], t3uY);
                t3vX = fmaf(cfP.y, x0[c3], t3vX);  t3vY = fmaf(cfQ.y, x1[c3], t3vY);
            }
            if (b2 == a) {
                t2uX = fmaf(t3uX, x0[b2], clP.x);  t2uY = fmaf(t3uY, x1[b2], clQ.x);
                t2vX = fmaf(t3vX, x0[b2], clP.y);  t2vY = fmaf(t3vY, x1[b2], clQ.y);
            } else {
                t2uX = fmaf(t3uX, x0[b2], t2uX);   t2uY = fmaf(t3uY, x1[b2], t2uY);
                t2vX = fmaf(t3vX, x0[b2], t2vX);   t2vY = fmaf(t3vY, x1[b2], t2vY);
            }
        }
        ouX = fmaf(t2uX, x0[a], ouX);  ouY = fmaf(t2uY, x1[a], ouY);
        ovX = fmaf(t2vX, x0[a], ovX);  ovY = fmaf(t2vY, x1[a], ovY);
    }

    // output: [b, 512] = concat(out0[b,c], out1[b, c*3+m])
    // slab half: h = (offset >= E_N*NT) -> comps {2h, 2h+1}
    int hP = (tk.z >= E_N * NT) ? 1 : 0;
    int hQ = (tk.w >= E_N * NT) ? 1 : 0;
    int aUP = hP ? (128 + c * 3 + 1) : c;
    int aVP = hP ? (128 + c * 3 + 2) : (128 + c * 3);
    int aUQ = hQ ? (128 + c * 3 + 1) : c;
    int aVQ = hQ ? (128 + c * 3 + 2) : (128 + c * 3);
    out[tk.x * 512 + aUP] = ouX;
    out[tk.x * 512 + aVP] = ovX;
    out[tk.y * 512 + aUQ] = ouY;
    out[tk.y * 512 + aVQ] = ovY;
}

// ---------------- launch --------------------------------------------------------
extern "C" void kernel_launch(void* const* d_in, const int* in_sizes, int n_in,
                              void* d_out, int out_size) {
    const float* a_i   = (const float*)d_in[0];
    const float* na    = (const float*)d_in[1];
    const float* U3_l0 = (const float*)d_in[2];
    const float* U2_l0 = (const float*)d_in[3];
    const float* U1_l0 = (const float*)d_in[4];
    const float* W3_l0 = (const float*)d_in[5];
    const float* W2_l0 = (const float*)d_in[6];
    const float* W1_l0 = (const float*)d_in[7];
    const float* U3_l1 = (const float*)d_in[8];
    const float* U2_l1 = (const float*)d_in[9];
    const float* U1_l1 = (const float*)d_in[10];
    const float* W3_l1 = (const float*)d_in[11];
    const float* W2_l1 = (const float*)d_in[12];
    const float* W1_l1 = (const float*)d_in[13];
    float* out = (float*)d_out;

    const int smem_bytes = 2 * E_N * NT * (int)sizeof(float2);  // 154880
    cudaFuncSetAttribute(main_kernel, cudaFuncAttributeMaxDynamicSharedMemorySize,
                         smem_bytes);

    prep_kernel<<<33, 1024>>>(na, U3_l0, U3_l1, U2_l0, U2_l1, U1_l0, U1_l1);
    main_kernel<<<C_N, 1024, smem_bytes>>>(a_i, W3_l0, W2_l0, W1_l0,
                                           W3_l1, W2_l1, W1_l1, out);
}